// round 16
// baseline (speedup 1.0000x reference)
#include <cuda_runtime.h>
#include <math.h>

#define TPB 256

// ---------------- shared-memory layout (floats) ----------------
// wfp   @0      [1200]  reflect-padded waveform
// cp    @1200   [1200]  reflect-padded cumsum
// dsp   @2400   [1200]  reflect-padded smoothed deriv
// buf   @3600   [1024]  d1-prefix / comp / final
// fnp   @4624   [3456]  3 slabs x 1152: zeros[0,54) | reflect10 | fn@64 | reflect10 | zeros
// f2v   @8080   [1560]  15 ch x (52 left | 52 right) virtual f2
// cwp   @9640   [1560]  W-folded comb weights 15 x 104
// wsubp @11200  [1080]  15 x 3 x 24 (invS folded before use)
// wcaE  @12280  [124]
// wxP   @12404  [124]
// wdvP  @12528  [124]
// keff  @12652  [372]   composite kernel 3 x 124 (W and invS folded)
// red   @13024  [32]
// scal  @13056  [16]
#define SMEM_FLOATS 13072
#define SLAB 1152

__device__ __align__(16) float g_K3[1116];
__device__ __align__(16) float g_wcaEff[124];
__device__ float g_speMax;

// ================= precompute kernel (once per launch) =================
__global__ void Spot_pre_kernel(const float* __restrict__ spe,
                                const float* __restrict__ wca,
                                const float* __restrict__ wrl,
                                const float* __restrict__ wsub,
                                const float* __restrict__ wcomb){
  __shared__ float red[32];
  __shared__ float sh[2];
  int tid=threadIdx.x, lane=tid&31, wid=tid>>5;

  float m=-1e30f;
  for(int i=tid;i<1000;i+=TPB) m=fmaxf(m,spe[i]);
#pragma unroll
  for(int o=16;o>0;o>>=1) m=fmaxf(m,__shfl_xor_sync(0xffffffffu,m,o));
  if(lane==0) red[wid]=m;
  __syncthreads();
  if(tid==0){ float mm=red[0]; for(int i=1;i<TPB/32;i++) mm=fmaxf(mm,red[i]);
              sh[0]=mm; g_speMax=mm; }
  __syncthreads();

  float s=0.f;
  for(int i=tid;i<121;i+=TPB) s+=wca[i];
#pragma unroll
  for(int o=16;o>0;o>>=1) s+=__shfl_xor_sync(0xffffffffu,s,o);
  if(lane==0) red[wid]=s;
  __syncthreads();
  if(tid==0){ float ss=0; for(int i=0;i<TPB/32;i++) ss+=red[i]; sh[1]=ss; }
  __syncthreads();
  float swca=sh[1];

  for(int i=tid;i<124;i+=TPB){
    float a =(i<121)? wca[i]:0.f;
    float rl=(i<101)? wrl[i]:0.f;
    g_wcaEff[i]=a - swca*rl;
  }

  // K3[r][c][q] = sum_d sum_k wsub[3d+r][c][k] * wcomb[d][q-k][r]
  for(int e=tid;e<1116;e+=TPB){
    int r=e/372, rem=e-r*372, c=rem/124, q=rem-c*124;
    float acc=0.f;
    if(q<121){
      int klo=(q>100)? (q-100):0;
      int khi=(q<20)? q:20;
      float ad[5]={0,0,0,0,0};
      for(int d=0;d<5;d++){
        const float* ws = wsub + ((3*d+r)*3+c)*21;
        float a2=0.f;
        for(int k=klo;k<=khi;k++)
          a2 = fmaf(ws[k], wcomb[(d*101+(q-k))*3+r], a2);
        ad[d]=a2;
      }
      acc=((ad[0]+ad[1])+(ad[2]+ad[3]))+ad[4];
    }
    g_K3[e]=acc;
  }
}

// ================= conv helpers =================
#define CONV4_BODY(x0,x1,wv,acc)                                               \
  acc[0]=fmaf(wv.x,x0.x,acc[0]); acc[1]=fmaf(wv.x,x0.y,acc[1]);                \
  acc[2]=fmaf(wv.x,x0.z,acc[2]); acc[3]=fmaf(wv.x,x0.w,acc[3]);                \
  acc[0]=fmaf(wv.y,x0.y,acc[0]); acc[1]=fmaf(wv.y,x0.z,acc[1]);                \
  acc[2]=fmaf(wv.y,x0.w,acc[2]); acc[3]=fmaf(wv.y,x1.x,acc[3]);                \
  acc[0]=fmaf(wv.z,x0.z,acc[0]); acc[1]=fmaf(wv.z,x0.w,acc[1]);                \
  acc[2]=fmaf(wv.z,x1.x,acc[2]); acc[3]=fmaf(wv.z,x1.y,acc[3]);                \
  acc[0]=fmaf(wv.w,x0.w,acc[0]); acc[1]=fmaf(wv.w,x1.x,acc[1]);                \
  acc[2]=fmaf(wv.w,x1.y,acc[2]); acc[3]=fmaf(wv.w,x1.z,acc[3]);

template<int NG>
__device__ __forceinline__ void conv4(const float* __restrict__ src,
                                      const float* __restrict__ w,
                                      float* __restrict__ acc){
  float4 x0 = *reinterpret_cast<const float4*>(src);
#pragma unroll
  for(int g=0; g<NG; g++){
    float4 x1 = *reinterpret_cast<const float4*>(src + 4*g + 4);
    float4 wv = *reinterpret_cast<const float4*>(w + 4*g);
    CONV4_BODY(x0,x1,wv,acc)
    x0=x1;
  }
}
__device__ __forceinline__ void conv4r(const float* __restrict__ src,
                                       const float* __restrict__ w,
                                       int ng, float* __restrict__ acc){
  float4 x0 = *reinterpret_cast<const float4*>(src);
#pragma unroll 4
  for(int g=0; g<ng; g++){
    float4 x1 = *reinterpret_cast<const float4*>(src + 4*g + 4);
    float4 wv = *reinterpret_cast<const float4*>(w + 4*g);
    CONV4_BODY(x0,x1,wv,acc)
    x0=x1;
  }
}
// two-channel fused conv: independent accs, 4 LDS + 32 FFMA per group
__device__ __forceinline__ void conv4x2(const float* __restrict__ s0,
                                        const float* __restrict__ s1,
                                        const float* __restrict__ w0,
                                        const float* __restrict__ w1,
                                        int ng,
                                        float* __restrict__ a0,
                                        float* __restrict__ a1){
  float4 p0 = *reinterpret_cast<const float4*>(s0);
  float4 q0 = *reinterpret_cast<const float4*>(s1);
#pragma unroll 2
  for(int g=0; g<ng; g++){
    float4 p1 = *reinterpret_cast<const float4*>(s0 + 4*g + 4);
    float4 q1 = *reinterpret_cast<const float4*>(s1 + 4*g + 4);
    float4 wa = *reinterpret_cast<const float4*>(w0 + 4*g);
    float4 wb = *reinterpret_cast<const float4*>(w1 + 4*g);
    CONV4_BODY(p0,p1,wa,a0)
    CONV4_BODY(q0,q1,wb,a1)
    p0=p1; q0=q1;
  }
}

// ================= reduction helpers =================
__device__ __forceinline__ float warpRMax(float v){
#pragma unroll
  for(int o=16;o>0;o>>=1) v=fmaxf(v,__shfl_xor_sync(0xffffffffu,v,o));
  return v;
}
__device__ __forceinline__ float warpRSum(float v){
#pragma unroll
  for(int o=16;o>0;o>>=1) v+=__shfl_xor_sync(0xffffffffu,v,o);
  return v;
}
__device__ __forceinline__ void bredSum(float v, float* red, float* out){
  int lane=threadIdx.x&31, wid=threadIdx.x>>5;
  v=warpRSum(v);
  if(lane==0) red[wid]=v;
  __syncthreads();
  if(threadIdx.x==0){
    float s=red[0];
#pragma unroll
    for(int i=1;i<TPB/32;i++) s+=red[i];
    *out=s;
  }
  __syncthreads();
}

__device__ __forceinline__ float softplusf(float v){
  return (v>0.f) ? v + log1pf(__expf(-v)) : log1pf(__expf(v));
}

// virtual f2 unit u in [0,390): m=u/26, side, group j. 4 outputs.
__device__ __forceinline__ void f2v_unit(int u, const float* __restrict__ fnp,
                                         const float* __restrict__ wsubp,
                                         float* __restrict__ f2v){
  int m=u/26, r26=u-26*m, side=r26/13, j=r26-13*side;
  int soff = side? (1052+4*j) : (4+4*j);
  float acc[4]={0,0,0,0};
  const float* wm = wsubp + m*72;
  conv4<6>(fnp          + soff, wm   , acc);
  conv4<6>(fnp +   SLAB + soff, wm+24, acc);
  conv4<6>(fnp + 2*SLAB + soff, wm+48, acc);
  float* o = f2v + m*104 + side*52 + 4*j;
  o[0]=acc[0]; o[1]=acc[1]; o[2]=acc[2]; o[3]=acc[3];
}

// ================= main kernel =================
__global__ void __launch_bounds__(TPB,4) Spot_48610439856277_kernel(
  const float* __restrict__ g_wf, const float* __restrict__ g_mask,
  const float* __restrict__ g_wx, const float* __restrict__ g_wdv,
  const float* __restrict__ g_wsub, const float* __restrict__ g_wcomb,
  const float* __restrict__ g_wp,
  float* __restrict__ g_out)
{
  extern __shared__ float sm[];
  float* wfp  = sm;
  float* cp   = sm + 1200;
  float* dsp  = sm + 2400;
  float* buf  = sm + 3600;
  float* fnp  = sm + 4624;
  float* f2v  = sm + 8080;
  float* cwp  = sm + 9640;
  float* wsubp= sm + 11200;
  float* wcaE = sm + 12280;
  float* wxP  = sm + 12404;
  float* wdvP = sm + 12528;
  float* keff = sm + 12652;
  float* red  = sm + 13024;
  float* scal = sm + 13056;

  const int tid = threadIdx.x;
  const int lane = tid&31, wid = tid>>5;
  const int b   = blockIdx.x;
  const float* wf = g_wf  + (size_t)b*1000;
  const float* mk = g_mask+ (size_t)b*1000;
  float* outp     = g_out + (size_t)b*1000;

  // ---- preamble loads + pads ----
  for(int i=tid;i<1200;i+=TPB){
    int j=i-100; j = (j<0) ? -j : (j>999 ? 1998-j : j);
    wfp[i]=wf[j];
  }
  for(int i=tid;i<124;i+=TPB){
    wcaE[i]=g_wcaEff[i];
    wxP[i] =(i<121)? g_wx[i] :0.f;
    wdvP[i]=(i<121)? g_wdv[i]:0.f;
  }
  for(int i=tid;i<1080;i+=TPB){
    int m=i/72, rem=i%72, cin=rem/24, k=rem%24;
    wsubp[i] = (k<21)? g_wsub[(m*3+cin)*21+k] : 0.f;
  }
  // fnp slab zero pads: [0,54) and [1074,1132) per slab
  for(int i=tid;i<3*112;i+=TPB){
    int c=i/112, j=i%112;
    int off = (j<54)? j : (1074 + (j-54));
    fnp[c*SLAB+off]=0.f;
  }
  __syncthreads();

  // ================= Phase A: fused dual scan (cumsum + d1-prefix) + wf max
  {
    int t0=4*tid;
    float la0=0,la1=0,la2=0,la3=0;
    float ld0=0,ld1=0,ld2=0,ld3=0;
    float vmax=-1e30f;
    if(t0<1000){
      float a0=wfp[100+t0], a1=wfp[101+t0], a2=wfp[102+t0], a3=wfp[103+t0];
      la0=a0; la1=la0+a1; la2=la1+a2; la3=la2+a3;
      vmax=fmaxf(fmaxf(a0,a1),fmaxf(a2,a3));
      const float dw0=1.f/280.f, dw1=-4.f/105.f, dw2=0.2f, dw3=-0.8f,
                  dw5=0.8f, dw6=-0.2f, dw7=4.f/105.f, dw8=-1.f/280.f;
#pragma unroll
      for(int j=0;j<4;j++){
        int t=t0+j;
        float s=0.f;
        if(t>=4)    s=fmaf(dw0, wfp[ 96+t], s);
        if(t>=3)    s=fmaf(dw1, wfp[ 97+t], s);
        if(t>=2)    s=fmaf(dw2, wfp[ 98+t], s);
        if(t>=1)    s=fmaf(dw3, wfp[ 99+t], s);
        if(t<=998)  s=fmaf(dw5, wfp[101+t], s);
        if(t<=997)  s=fmaf(dw6, wfp[102+t], s);
        if(t<=996)  s=fmaf(dw7, wfp[103+t], s);
        if(t<=995)  s=fmaf(dw8, wfp[104+t], s);
        if(j==0){ ld0=s; } else if(j==1){ ld1=ld0+s; }
        else if(j==2){ ld2=ld1+s; } else { ld3=ld2+s; }
      }
    }
    float csA=la3, xA=csA, csB=ld3, xB=csB;
#pragma unroll
    for(int o=1;o<32;o<<=1){
      float yA=__shfl_up_sync(0xffffffffu,xA,o); if(lane>=o) xA+=yA;
      float yB=__shfl_up_sync(0xffffffffu,xB,o); if(lane>=o) xB+=yB;
    }
    if(lane==31){ red[wid]=xA; red[8+wid]=xB; }
    float wm=warpRMax(vmax);
    if(lane==0) red[16+wid]=wm;
    __syncthreads();
    if(wid==0){
      float z=(lane<8)? red[lane]:0.f;
#pragma unroll
      for(int o=1;o<8;o<<=1){ float y=__shfl_up_sync(0xffffffffu,z,o); if(lane>=o) z+=y; }
      if(lane<8) red[lane]=z;
    } else if(wid==1){
      float z=(lane<8)? red[8+lane]:0.f;
#pragma unroll
      for(int o=1;o<8;o<<=1){ float y=__shfl_up_sync(0xffffffffu,z,o); if(lane>=o) z+=y; }
      if(lane<8) red[8+lane]=z;
    } else if(wid==2 && lane==0){
      float m=red[16];
#pragma unroll
      for(int i=17;i<24;i++) m=fmaxf(m,red[i]);
      scal[0]=m;
    }
    __syncthreads();
    float preA = xA - csA + ((wid>0)? red[wid-1]:0.f);
    float preB = xB - csB + ((wid>0)? red[8+wid-1]:0.f);
    if(t0<1000){
      cp[100+t0]=preA+la0; cp[101+t0]=preA+la1;
      cp[102+t0]=preA+la2; cp[103+t0]=preA+la3;
      buf[t0  ]=preB+ld0; buf[t0+1]=preB+ld1;
      buf[t0+2]=preB+ld2; buf[t0+3]=preB+ld3;
    }
    if(tid==0){
      float h = scal[0]/g_speMax;
      float e0=-fmaxf(h-g_wp[0],0.f);
      float e1=-fmaxf(h-g_wp[1],0.f);
      float e2=-fmaxf(h-g_wp[2],0.f);
      float mg=fmaxf(e0,fmaxf(e1,e2));
      float p0=__expf(e0-mg),p1=__expf(e1-mg),p2=__expf(e2-mg);
      float is=1.f/(p0+p1+p2);
      scal[3]=p0*is; scal[4]=p1*is; scal[5]=p2*is;
    }
  }
  __syncthreads();

  // ================= Phase B: cp halos, dsp from prefixes, cwp build
  for(int i=tid;i<100;i+=TPB){ cp[i]=cp[200-i]; cp[1100+i]=cp[1098-i]; }
  for(int t=tid;t<1000;t+=TPB){
    int hi = (t+25>999)? 999 : t+25;
    float p = buf[hi] - ((t>=26)? buf[t-26] : 0.f);
    dsp[100+t]=p*(1.f/51.f);
  }
  for(int i=tid;i<100;i+=TPB){
    int tm=100-i;
    dsp[i] = (buf[tm+25] - ((tm>=26)? buf[tm-26]:0.f))*(1.f/51.f);
    int tr=998-i;
    int hi=(tr+25>999)? 999 : tr+25;
    dsp[1100+i] = (buf[hi] - buf[tr-26])*(1.f/51.f);
  }
  for(int i=tid;i<1560;i+=TPB){
    int c=i/104, hh=i%104, d=c/3, r=c%3;
    cwp[i] = (hh<101) ? scal[3+r]*g_wcomb[(d*101+hh)*3+r] : 0.f;
  }
  __syncthreads();

  // ================= Phase C: fit convs (c0+c1 fused, c2 scalar) + inline sums
  float ls0=0.f, ls1=0.f, ls2=0.f;
  if(tid<250){
    int t0=4*tid;
    float a[4]={0,0,0,0}, bb[4]={0,0,0,0};
    conv4x2(cp+t0, wfp+t0, wcaE, wxP, 31, a, bb);
#pragma unroll
    for(int j=0;j<4;j++){
      float r0=fmaxf(a[j],0.f);  fnp[64+t0+j]=r0;      ls0+=r0;
      float r1=fmaxf(bb[j],0.f); fnp[SLAB+64+t0+j]=r1; ls1+=r1;
    }
    float c[4]={0,0,0,0};
    conv4r(dsp+t0, wdvP, 31, c);
#pragma unroll
    for(int j=0;j<4;j++){ float r=fmaxf(c[j],0.f); fnp[2*SLAB+64+t0+j]=r; ls2+=r; }
  }
  {
    float s0=warpRSum(ls0), s1=warpRSum(ls1), s2=warpRSum(ls2);
    if(lane==0){ red[wid]=s0; red[8+wid]=s1; red[16+wid]=s2; }
    __syncthreads();
    if(tid==0){
      float S0=0,S1=0,S2=0;
#pragma unroll
      for(int i=0;i<8;i++){ S0+=red[i]; S1+=red[8+i]; S2+=red[16+i]; }
      scal[6]=1.f/(S0+1e-10f); scal[7]=1.f/(S1+1e-10f); scal[8]=1.f/(S2+1e-10f);
    }
    __syncthreads();
  }

  // ================= Phase D: slab reflect halos, keff build, wsubp*=invS
  for(int i=tid;i<60;i+=TPB){
    int c=i/20, q=i%20;
    float* f=fnp+c*SLAB;
    if(q<10) f[63-q]=f[65+q];
    else { int j=q-10; f[1064+j]=f[1062-j]; }
  }
  for(int i=tid;i<372;i+=TPB){
    int c=i/124;
    keff[i] = (scal[3]*g_K3[i] + scal[4]*g_K3[372+i] + scal[5]*g_K3[744+i])*scal[6+c];
  }
  for(int i=tid;i<1080;i+=TPB){
    int c=(i%72)/24;
    wsubp[i]*=scal[6+c];
  }
  __syncthreads();

  // ================= Phase EF: full composite (c0+c1 fused) + virtual f2
  if(tid<250){
    int t0=4*tid;
    float a[4]={0,0,0,0}, bb[4]={0,0,0,0};
    conv4x2(fnp + t0 + 4, fnp + SLAB + t0 + 4, keff, keff+124, 31, a, bb);
    float c[4]={0,0,0,0};
    conv4r(fnp + 2*SLAB + t0 + 4, keff+248, 31, c);
#pragma unroll
    for(int j=0;j<4;j++){
      int t=t0+j;
      float v=(a[j]+bb[j])+c[j];
      buf[t] = (t>=50 && t<950) ? softplusf(v) : v;
    }
    f2v_unit(30+tid, fnp, wsubp, f2v);
    if(tid<110) f2v_unit(280+tid, fnp, wsubp, f2v);
  } else {
#pragma unroll 1
    for(int q=0;q<5;q++) f2v_unit((tid-250)+6*q, fnp, wsubp, f2v);
  }
  __syncthreads();

  // ================= Phase G: boundary corrections + softplus
  if(tid<100){
    float corr=0.f;
    int t;
    if(tid<50){
      t=tid;
      int n=50-t;
#pragma unroll 1
      for(int c=0;c<15;c++){
        const float* cw=cwp+c*104;
        const float* fv=f2v+c*104+t;
        float s=0.f;
        for(int h=0;h<n;h++) s=fmaf(cw[h],fv[h],s);
        corr+=s;
      }
    } else {
      t=900+tid;   // 950..999
      int n=t-949, h0=1050-t;
#pragma unroll 1
      for(int c=0;c<15;c++){
        const float* cw=cwp+c*104+h0;
        const float* fv=f2v+c*104+54;
        float s=0.f;
        for(int i=0;i<n;i++) s=fmaf(cw[i],fv[i],s);
        corr+=s;
      }
    }
    buf[t]=softplusf(buf[t]-corr);
  }
  __syncthreads();

  // ================= epilogue: fused amax/mmax, 1e4-softmax (3 sweeps)
  {
    float om=-1e30f, mm=-1e30f;
    for(int t=tid;t<1000;t+=TPB){
      float v=buf[t];
      om=fmaxf(om,v);
      mm=fmaxf(mm,v*mk[t]);
    }
    om=warpRMax(om); mm=warpRMax(mm);
    if(lane==0){ red[wid]=om; red[8+wid]=mm; }
    __syncthreads();
    if(tid==0){
      float a=red[0], m2=red[8];
#pragma unroll
      for(int i=1;i<8;i++){ a=fmaxf(a,red[i]); m2=fmaxf(m2,red[8+i]); }
      scal[9]=a; scal[10]=m2;
    }
    __syncthreads();
    float amax = scal[9] + 1e-10f;
    float ymax = 1e4f*(scal[10]/amax);   // shift constant; offset cancels in softmax

    float ssum=0.f;
    for(int t=tid;t<1000;t+=TPB){
      float y = 1e4f * ((buf[t]/amax)*mk[t]);
      float p=__expf(y-ymax);
      buf[t]=p; ssum+=p;
    }
    bredSum(ssum,red,&scal[11]);
    float isum=1.f/scal[11];
    for(int t=tid;t<1000;t+=TPB) outp[t]=buf[t]*isum;
  }
}

extern "C" void kernel_launch(void* const* d_in, const int* in_sizes, int n_in,
                              void* d_out, int out_size) {
  const float* wf    = (const float*)d_in[0];
  const float* mask  = (const float*)d_in[1];
  const float* SPE   = (const float*)d_in[2];
  const float* wca   = (const float*)d_in[3];
  const float* wx    = (const float*)d_in[4];
  const float* wdv   = (const float*)d_in[5];
  const float* wrl   = (const float*)d_in[6];
  const float* wsub  = (const float*)d_in[7];
  const float* wcomb = (const float*)d_in[8];
  const float* wp    = (const float*)d_in[9];
  float* out = (float*)d_out;

  int B = in_sizes[0] / 1000;
  size_t smem = SMEM_FLOATS * sizeof(float);
  cudaFuncSetAttribute(Spot_48610439856277_kernel,
                       cudaFuncAttributeMaxDynamicSharedMemorySize, (int)smem);

  Spot_pre_kernel<<<1, TPB>>>(SPE, wca, wrl, wsub, wcomb);
  Spot_48610439856277_kernel<<<B, TPB, smem>>>(wf, mask, wx, wdv,
                                               wsub, wcomb, wp, out);
}

// round 17
// speedup vs baseline: 1.0460x; 1.0460x over previous
#include <cuda_runtime.h>
#include <math.h>

#define TPB 256

// ---------------- shared-memory layout (floats) ----------------
// Phase A-C:  wfp @0 [1200] | cp @1200 [1200] | dsp @2400 [1200]
// Phase D-G:  cwp @0 [1560] | f2v @1560 [1560]   (overlay: wfp/cp/dsp dead)
// buf   @3600   [1024]  d1-prefix / comp / final
// fnp   @4624   [3456]  3 slabs x 1152
// wsubp @8080   [1080]
// wcaE  @9160   [124]
// wxP   @9284   [124]
// wdvP  @9408   [124]
// keff  @9532   [372]
// red   @9904   [32]
// scal  @9936   [16]
#define SMEM_FLOATS 9952
#define SLAB 1152

__device__ __align__(16) float g_K3[1116];
__device__ __align__(16) float g_wcaEff[124];
__device__ float g_speMax;

// ================= precompute kernel (once per launch) =================
__global__ void Spot_pre_kernel(const float* __restrict__ spe,
                                const float* __restrict__ wca,
                                const float* __restrict__ wrl,
                                const float* __restrict__ wsub,
                                const float* __restrict__ wcomb){
  __shared__ float red[32];
  __shared__ float sh[2];
  int tid=threadIdx.x, lane=tid&31, wid=tid>>5;

  float m=-1e30f;
  for(int i=tid;i<1000;i+=TPB) m=fmaxf(m,spe[i]);
#pragma unroll
  for(int o=16;o>0;o>>=1) m=fmaxf(m,__shfl_xor_sync(0xffffffffu,m,o));
  if(lane==0) red[wid]=m;
  __syncthreads();
  if(tid==0){ float mm=red[0]; for(int i=1;i<TPB/32;i++) mm=fmaxf(mm,red[i]);
              sh[0]=mm; g_speMax=mm; }
  __syncthreads();

  float s=0.f;
  for(int i=tid;i<121;i+=TPB) s+=wca[i];
#pragma unroll
  for(int o=16;o>0;o>>=1) s+=__shfl_xor_sync(0xffffffffu,s,o);
  if(lane==0) red[wid]=s;
  __syncthreads();
  if(tid==0){ float ss=0; for(int i=0;i<TPB/32;i++) ss+=red[i]; sh[1]=ss; }
  __syncthreads();
  float swca=sh[1];

  for(int i=tid;i<124;i+=TPB){
    float a =(i<121)? wca[i]:0.f;
    float rl=(i<101)? wrl[i]:0.f;
    g_wcaEff[i]=a - swca*rl;
  }

  // K3[r][c][q] = sum_d sum_k wsub[3d+r][c][k] * wcomb[d][q-k][r]
  for(int e=tid;e<1116;e+=TPB){
    int r=e/372, rem=e-r*372, c=rem/124, q=rem-c*124;
    float acc=0.f;
    if(q<121){
      int klo=(q>100)? (q-100):0;
      int khi=(q<20)? q:20;
      float ad[5]={0,0,0,0,0};
      for(int d=0;d<5;d++){
        const float* ws = wsub + ((3*d+r)*3+c)*21;
        float a2=0.f;
        for(int k=klo;k<=khi;k++)
          a2 = fmaf(ws[k], wcomb[(d*101+(q-k))*3+r], a2);
        ad[d]=a2;
      }
      acc=((ad[0]+ad[1])+(ad[2]+ad[3]))+ad[4];
    }
    g_K3[e]=acc;
  }
}

// ================= conv helpers =================
#define CONV4_BODY(x0,x1,wv,acc)                                               \
  acc[0]=fmaf(wv.x,x0.x,acc[0]); acc[1]=fmaf(wv.x,x0.y,acc[1]);                \
  acc[2]=fmaf(wv.x,x0.z,acc[2]); acc[3]=fmaf(wv.x,x0.w,acc[3]);                \
  acc[0]=fmaf(wv.y,x0.y,acc[0]); acc[1]=fmaf(wv.y,x0.z,acc[1]);                \
  acc[2]=fmaf(wv.y,x0.w,acc[2]); acc[3]=fmaf(wv.y,x1.x,acc[3]);                \
  acc[0]=fmaf(wv.z,x0.z,acc[0]); acc[1]=fmaf(wv.z,x0.w,acc[1]);                \
  acc[2]=fmaf(wv.z,x1.x,acc[2]); acc[3]=fmaf(wv.z,x1.y,acc[3]);                \
  acc[0]=fmaf(wv.w,x0.w,acc[0]); acc[1]=fmaf(wv.w,x1.x,acc[1]);                \
  acc[2]=fmaf(wv.w,x1.y,acc[2]); acc[3]=fmaf(wv.w,x1.z,acc[3]);

template<int NG>
__device__ __forceinline__ void conv4(const float* __restrict__ src,
                                      const float* __restrict__ w,
                                      float* __restrict__ acc){
  float4 x0 = *reinterpret_cast<const float4*>(src);
#pragma unroll
  for(int g=0; g<NG; g++){
    float4 x1 = *reinterpret_cast<const float4*>(src + 4*g + 4);
    float4 wv = *reinterpret_cast<const float4*>(w + 4*g);
    CONV4_BODY(x0,x1,wv,acc)
    x0=x1;
  }
}
__device__ __forceinline__ void conv4r(const float* __restrict__ src,
                                       const float* __restrict__ w,
                                       int ng, float* __restrict__ acc){
  float4 x0 = *reinterpret_cast<const float4*>(src);
#pragma unroll 4
  for(int g=0; g<ng; g++){
    float4 x1 = *reinterpret_cast<const float4*>(src + 4*g + 4);
    float4 wv = *reinterpret_cast<const float4*>(w + 4*g);
    CONV4_BODY(x0,x1,wv,acc)
    x0=x1;
  }
}

// ================= reduction helpers =================
__device__ __forceinline__ float warpRMax(float v){
#pragma unroll
  for(int o=16;o>0;o>>=1) v=fmaxf(v,__shfl_xor_sync(0xffffffffu,v,o));
  return v;
}
__device__ __forceinline__ float warpRSum(float v){
#pragma unroll
  for(int o=16;o>0;o>>=1) v+=__shfl_xor_sync(0xffffffffu,v,o);
  return v;
}
__device__ __forceinline__ void bredSum(float v, float* red, float* out){
  int lane=threadIdx.x&31, wid=threadIdx.x>>5;
  v=warpRSum(v);
  if(lane==0) red[wid]=v;
  __syncthreads();
  if(threadIdx.x==0){
    float s=red[0];
#pragma unroll
    for(int i=1;i<TPB/32;i++) s+=red[i];
    *out=s;
  }
  __syncthreads();
}

__device__ __forceinline__ float softplusf(float v){
  return (v>0.f) ? v + log1pf(__expf(-v)) : log1pf(__expf(v));
}

// virtual f2 unit u in [0,390): m=u/26, side, group j. 4 outputs.
__device__ __forceinline__ void f2v_unit(int u, const float* __restrict__ fnp,
                                         const float* __restrict__ wsubp,
                                         float* __restrict__ f2v){
  int m=u/26, r26=u-26*m, side=r26/13, j=r26-13*side;
  int soff = side? (1052+4*j) : (4+4*j);
  float acc[4]={0,0,0,0};
  const float* wm = wsubp + m*72;
  conv4<6>(fnp          + soff, wm   , acc);
  conv4<6>(fnp +   SLAB + soff, wm+24, acc);
  conv4<6>(fnp + 2*SLAB + soff, wm+48, acc);
  float* o = f2v + m*104 + side*52 + 4*j;
  o[0]=acc[0]; o[1]=acc[1]; o[2]=acc[2]; o[3]=acc[3];
}

// ================= main kernel =================
__global__ void __launch_bounds__(TPB,5) Spot_48610439856277_kernel(
  const float* __restrict__ g_wf, const float* __restrict__ g_mask,
  const float* __restrict__ g_wx, const float* __restrict__ g_wdv,
  const float* __restrict__ g_wsub, const float* __restrict__ g_wcomb,
  const float* __restrict__ g_wp,
  float* __restrict__ g_out)
{
  extern __shared__ float sm[];
  float* wfp  = sm;            // dead after Phase C
  float* cp   = sm + 1200;     // dead after Phase C
  float* dsp  = sm + 2400;     // dead after Phase C
  float* cwp  = sm;            // overlay, built in Phase D
  float* f2v  = sm + 1560;     // overlay, written in Phase EF
  float* buf  = sm + 3600;
  float* fnp  = sm + 4624;
  float* wsubp= sm + 8080;
  float* wcaE = sm + 9160;
  float* wxP  = sm + 9284;
  float* wdvP = sm + 9408;
  float* keff = sm + 9532;
  float* red  = sm + 9904;
  float* scal = sm + 9936;

  const int tid = threadIdx.x;
  const int lane = tid&31, wid = tid>>5;
  const int b   = blockIdx.x;
  const float* wf = g_wf  + (size_t)b*1000;
  const float* mk = g_mask+ (size_t)b*1000;
  float* outp     = g_out + (size_t)b*1000;

  // ---- preamble loads + pads ----
  for(int i=tid;i<1200;i+=TPB){
    int j=i-100; j = (j<0) ? -j : (j>999 ? 1998-j : j);
    wfp[i]=wf[j];
  }
  for(int i=tid;i<124;i+=TPB){
    wcaE[i]=g_wcaEff[i];
    wxP[i] =(i<121)? g_wx[i] :0.f;
    wdvP[i]=(i<121)? g_wdv[i]:0.f;
  }
  for(int i=tid;i<1080;i+=TPB){
    int m=i/72, rem=i%72, cin=rem/24, k=rem%24;
    wsubp[i] = (k<21)? g_wsub[(m*3+cin)*21+k] : 0.f;
  }
  // fnp slab zero pads: [0,54) and [1074,1132) per slab
  for(int i=tid;i<3*112;i+=TPB){
    int c=i/112, j=i%112;
    int off = (j<54)? j : (1074 + (j-54));
    fnp[c*SLAB+off]=0.f;
  }
  __syncthreads();

  // ================= Phase A: fused dual scan (cumsum + d1-prefix) + wf max
  {
    int t0=4*tid;
    float la0=0,la1=0,la2=0,la3=0;
    float ld0=0,ld1=0,ld2=0,ld3=0;
    float vmax=-1e30f;
    if(t0<1000){
      float a0=wfp[100+t0], a1=wfp[101+t0], a2=wfp[102+t0], a3=wfp[103+t0];
      la0=a0; la1=la0+a1; la2=la1+a2; la3=la2+a3;
      vmax=fmaxf(fmaxf(a0,a1),fmaxf(a2,a3));
      const float dw0=1.f/280.f, dw1=-4.f/105.f, dw2=0.2f, dw3=-0.8f,
                  dw5=0.8f, dw6=-0.2f, dw7=4.f/105.f, dw8=-1.f/280.f;
#pragma unroll
      for(int j=0;j<4;j++){
        int t=t0+j;
        float s=0.f;
        if(t>=4)    s=fmaf(dw0, wfp[ 96+t], s);
        if(t>=3)    s=fmaf(dw1, wfp[ 97+t], s);
        if(t>=2)    s=fmaf(dw2, wfp[ 98+t], s);
        if(t>=1)    s=fmaf(dw3, wfp[ 99+t], s);
        if(t<=998)  s=fmaf(dw5, wfp[101+t], s);
        if(t<=997)  s=fmaf(dw6, wfp[102+t], s);
        if(t<=996)  s=fmaf(dw7, wfp[103+t], s);
        if(t<=995)  s=fmaf(dw8, wfp[104+t], s);
        if(j==0){ ld0=s; } else if(j==1){ ld1=ld0+s; }
        else if(j==2){ ld2=ld1+s; } else { ld3=ld2+s; }
      }
    }
    float csA=la3, xA=csA, csB=ld3, xB=csB;
#pragma unroll
    for(int o=1;o<32;o<<=1){
      float yA=__shfl_up_sync(0xffffffffu,xA,o); if(lane>=o) xA+=yA;
      float yB=__shfl_up_sync(0xffffffffu,xB,o); if(lane>=o) xB+=yB;
    }
    if(lane==31){ red[wid]=xA; red[8+wid]=xB; }
    float wm=warpRMax(vmax);
    if(lane==0) red[16+wid]=wm;
    __syncthreads();
    if(wid==0){
      float z=(lane<8)? red[lane]:0.f;
#pragma unroll
      for(int o=1;o<8;o<<=1){ float y=__shfl_up_sync(0xffffffffu,z,o); if(lane>=o) z+=y; }
      if(lane<8) red[lane]=z;
    } else if(wid==1){
      float z=(lane<8)? red[8+lane]:0.f;
#pragma unroll
      for(int o=1;o<8;o<<=1){ float y=__shfl_up_sync(0xffffffffu,z,o); if(lane>=o) z+=y; }
      if(lane<8) red[8+lane]=z;
    } else if(wid==2 && lane==0){
      float m=red[16];
#pragma unroll
      for(int i=17;i<24;i++) m=fmaxf(m,red[i]);
      scal[0]=m;
    }
    __syncthreads();
    float preA = xA - csA + ((wid>0)? red[wid-1]:0.f);
    float preB = xB - csB + ((wid>0)? red[8+wid-1]:0.f);
    if(t0<1000){
      cp[100+t0]=preA+la0; cp[101+t0]=preA+la1;
      cp[102+t0]=preA+la2; cp[103+t0]=preA+la3;
      buf[t0  ]=preB+ld0; buf[t0+1]=preB+ld1;
      buf[t0+2]=preB+ld2; buf[t0+3]=preB+ld3;
    }
    if(tid==0){
      float h = scal[0]/g_speMax;
      float e0=-fmaxf(h-g_wp[0],0.f);
      float e1=-fmaxf(h-g_wp[1],0.f);
      float e2=-fmaxf(h-g_wp[2],0.f);
      float mg=fmaxf(e0,fmaxf(e1,e2));
      float p0=__expf(e0-mg),p1=__expf(e1-mg),p2=__expf(e2-mg);
      float is=1.f/(p0+p1+p2);
      scal[3]=p0*is; scal[4]=p1*is; scal[5]=p2*is;
    }
  }
  __syncthreads();

  // ================= Phase B: cp halos, dsp from prefixes
  for(int i=tid;i<100;i+=TPB){ cp[i]=cp[200-i]; cp[1100+i]=cp[1098-i]; }
  for(int t=tid;t<1000;t+=TPB){
    int hi = (t+25>999)? 999 : t+25;
    float p = buf[hi] - ((t>=26)? buf[t-26] : 0.f);
    dsp[100+t]=p*(1.f/51.f);
  }
  for(int i=tid;i<100;i+=TPB){
    int tm=100-i;
    dsp[i] = (buf[tm+25] - ((tm>=26)? buf[tm-26]:0.f))*(1.f/51.f);
    int tr=998-i;
    int hi=(tr+25>999)? 999 : tr+25;
    dsp[1100+i] = (buf[hi] - buf[tr-26])*(1.f/51.f);
  }
  __syncthreads();

  // ================= Phase C: fit convs (raw relu -> slabs) + inline sums
  float ls0=0.f, ls1=0.f, ls2=0.f;
  if(tid<250){
    int t0=4*tid;
    {
      float a[4]={0,0,0,0};
      conv4r(cp +t0, wcaE, 31, a);
#pragma unroll
      for(int j=0;j<4;j++){ float r=fmaxf(a[j],0.f); fnp[64+t0+j]=r; ls0+=r; }
    }
    {
      float a[4]={0,0,0,0};
      conv4r(wfp+t0, wxP , 31, a);
#pragma unroll
      for(int j=0;j<4;j++){ float r=fmaxf(a[j],0.f); fnp[SLAB+64+t0+j]=r; ls1+=r; }
    }
    {
      float a[4]={0,0,0,0};
      conv4r(dsp+t0, wdvP, 31, a);
#pragma unroll
      for(int j=0;j<4;j++){ float r=fmaxf(a[j],0.f); fnp[2*SLAB+64+t0+j]=r; ls2+=r; }
    }
  }
  {
    float s0=warpRSum(ls0), s1=warpRSum(ls1), s2=warpRSum(ls2);
    if(lane==0){ red[wid]=s0; red[8+wid]=s1; red[16+wid]=s2; }
    __syncthreads();
    if(tid==0){
      float S0=0,S1=0,S2=0;
#pragma unroll
      for(int i=0;i<8;i++){ S0+=red[i]; S1+=red[8+i]; S2+=red[16+i]; }
      scal[6]=1.f/(S0+1e-10f); scal[7]=1.f/(S1+1e-10f); scal[8]=1.f/(S2+1e-10f);
    }
    __syncthreads();
  }

  // ================= Phase D: slab halos, cwp (overlay!) + keff + wsubp*=invS
  // wfp/cp/dsp are dead from here; cwp overlays sm[0..1560)
  for(int i=tid;i<60;i+=TPB){
    int c=i/20, q=i%20;
    float* f=fnp+c*SLAB;
    if(q<10) f[63-q]=f[65+q];
    else { int j=q-10; f[1064+j]=f[1062-j]; }
  }
  for(int i=tid;i<1560;i+=TPB){
    int c=i/104, hh=i%104, d=c/3, r=c%3;
    cwp[i] = (hh<101) ? scal[3+r]*g_wcomb[(d*101+hh)*3+r] : 0.f;
  }
  for(int i=tid;i<372;i+=TPB){
    int c=i/124;
    keff[i] = (scal[3]*g_K3[i] + scal[4]*g_K3[372+i] + scal[5]*g_K3[744+i])*scal[6+c];
  }
  for(int i=tid;i<1080;i+=TPB){
    int c=(i%72)/24;
    wsubp[i]*=scal[6+c];
  }
  __syncthreads();

  // ================= Phase EF: full composite (250 thr) + virtual f2 (390 units)
  if(tid<250){
    int t0=4*tid;
    float acc[4]={0,0,0,0};
    conv4r(fnp          + t0 + 4, keff    , 31, acc);
    conv4r(fnp +   SLAB + t0 + 4, keff+124, 31, acc);
    conv4r(fnp + 2*SLAB + t0 + 4, keff+248, 31, acc);
#pragma unroll
    for(int j=0;j<4;j++){
      int t=t0+j;
      buf[t] = (t>=50 && t<950) ? softplusf(acc[j]) : acc[j];
    }
    f2v_unit(30+tid, fnp, wsubp, f2v);
    if(tid<110) f2v_unit(280+tid, fnp, wsubp, f2v);
  } else {
#pragma unroll 1
    for(int q=0;q<5;q++) f2v_unit((tid-250)+6*q, fnp, wsubp, f2v);
  }
  __syncthreads();

  // ================= Phase G: boundary corrections + softplus
  if(tid<100){
    float corr=0.f;
    int t;
    if(tid<50){
      t=tid;
      int n=50-t;
#pragma unroll 1
      for(int c=0;c<15;c++){
        const float* cw=cwp+c*104;
        const float* fv=f2v+c*104+t;
        float s=0.f;
        for(int h=0;h<n;h++) s=fmaf(cw[h],fv[h],s);
        corr+=s;
      }
    } else {
      t=900+tid;   // 950..999
      int n=t-949, h0=1050-t;
#pragma unroll 1
      for(int c=0;c<15;c++){
        const float* cw=cwp+c*104+h0;
        const float* fv=f2v+c*104+54;
        float s=0.f;
        for(int i=0;i<n;i++) s=fmaf(cw[i],fv[i],s);
        corr+=s;
      }
    }
    buf[t]=softplusf(buf[t]-corr);
  }
  __syncthreads();

  // ================= epilogue: fused amax/mmax, 1e4-softmax (3 sweeps)
  {
    float om=-1e30f, mm=-1e30f;
    for(int t=tid;t<1000;t+=TPB){
      float v=buf[t];
      om=fmaxf(om,v);
      mm=fmaxf(mm,v*mk[t]);
    }
    om=warpRMax(om); mm=warpRMax(mm);
    if(lane==0){ red[wid]=om; red[8+wid]=mm; }
    __syncthreads();
    if(tid==0){
      float a=red[0], m2=red[8];
#pragma unroll
      for(int i=1;i<8;i++){ a=fmaxf(a,red[i]); m2=fmaxf(m2,red[8+i]); }
      scal[9]=a; scal[10]=m2;
    }
    __syncthreads();
    float amax = scal[9] + 1e-10f;
    float ymax = 1e4f*(scal[10]/amax);   // shift constant; offset cancels in softmax

    float ssum=0.f;
    for(int t=tid;t<1000;t+=TPB){
      float y = 1e4f * ((buf[t]/amax)*mk[t]);
      float p=__expf(y-ymax);
      buf[t]=p; ssum+=p;
    }
    bredSum(ssum,red,&scal[11]);
    float isum=1.f/scal[11];
    for(int t=tid;t<1000;t+=TPB) outp[t]=buf[t]*isum;
  }
}

extern "C" void kernel_launch(void* const* d_in, const int* in_sizes, int n_in,
                              void* d_out, int out_size) {
  const float* wf    = (const float*)d_in[0];
  const float* mask  = (const float*)d_in[1];
  const float* SPE   = (const float*)d_in[2];
  const float* wca   = (const float*)d_in[3];
  const float* wx    = (const float*)d_in[4];
  const float* wdv   = (const float*)d_in[5];
  const float* wrl   = (const float*)d_in[6];
  const float* wsub  = (const float*)d_in[7];
  const float* wcomb = (const float*)d_in[8];
  const float* wp    = (const float*)d_in[9];
  float* out = (float*)d_out;

  int B = in_sizes[0] / 1000;
  size_t smem = SMEM_FLOATS * sizeof(float);
  cudaFuncSetAttribute(Spot_48610439856277_kernel,
                       cudaFuncAttributeMaxDynamicSharedMemorySize, (int)smem);

  Spot_pre_kernel<<<1, TPB>>>(SPE, wca, wrl, wsub, wcomb);
  Spot_48610439856277_kernel<<<B, TPB, smem>>>(wf, mask, wx, wdv,
                                               wsub, wcomb, wp, out);
}